// round 5
// baseline (speedup 1.0000x reference)
#include <cuda_runtime.h>
#include <cuda_bf16.h>
#include <cstdint>

// Problem dims (fixed by the dataset)
#define M_TOK 4096            // B*S = 2*2048
#define HDIM  4096
#define IDIM  14336

// ---------------------------------------------------------------------------
// Device scratch (allocation-free rule: __device__ globals)
// ---------------------------------------------------------------------------
__device__ __nv_bfloat16 g_xq[(size_t)M_TOK * HDIM];      // quantized x (integer values in bf16)
__device__ float         g_xscale[M_TOK];                  // per-token scale
__device__ float         g_gate[(size_t)M_TOK * IDIM];
__device__ float         g_up  [(size_t)M_TOK * IDIM];
__device__ __nv_bfloat16 g_q2[(size_t)M_TOK * IDIM];       // quantized inter
__device__ float         g_s2[M_TOK];
__device__ __nv_bfloat16 g_wg_hi[(size_t)IDIM * HDIM];
__device__ __nv_bfloat16 g_wg_lo[(size_t)IDIM * HDIM];
__device__ __nv_bfloat16 g_wu_hi[(size_t)IDIM * HDIM];
__device__ __nv_bfloat16 g_wu_lo[(size_t)IDIM * HDIM];
__device__ __nv_bfloat16 g_wd_hi[(size_t)HDIM * IDIM];
__device__ __nv_bfloat16 g_wd_lo[(size_t)HDIM * IDIM];

// ---------------------------------------------------------------------------
// Small PTX helpers
// ---------------------------------------------------------------------------
__device__ __forceinline__ void cp_async16(void* smem_dst, const void* gmem_src) {
    uint32_t s = (uint32_t)__cvta_generic_to_shared(smem_dst);
    asm volatile("cp.async.cg.shared.global [%0], [%1], 16;\n" :: "r"(s), "l"(gmem_src));
}
__device__ __forceinline__ void cp_commit() { asm volatile("cp.async.commit_group;\n"); }
template<int N> __device__ __forceinline__ void cp_wait() {
    asm volatile("cp.async.wait_group %0;\n" :: "n"(N));
}
__device__ __forceinline__ void mma16816(float* c, const uint32_t* a, uint32_t b0, uint32_t b1) {
    asm volatile(
        "mma.sync.aligned.m16n8k16.row.col.f32.bf16.bf16.f32 "
        "{%0,%1,%2,%3},{%4,%5,%6,%7},{%8,%9},{%0,%1,%2,%3};\n"
        : "+f"(c[0]), "+f"(c[1]), "+f"(c[2]), "+f"(c[3])
        : "r"(a[0]), "r"(a[1]), "r"(a[2]), "r"(a[3]), "r"(b0), "r"(b1));
}

// ---------------------------------------------------------------------------
// 1) Split fp32 weights into bf16 hi/lo pairs (exact to ~2^-17 rel)
// ---------------------------------------------------------------------------
__global__ void split_w_kernel(const float* __restrict__ wg,
                               const float* __restrict__ wu,
                               const float* __restrict__ wd) {
    const size_t n1 = (size_t)IDIM * HDIM;
    const size_t total = 3 * n1;
    size_t stride = (size_t)gridDim.x * blockDim.x;
    for (size_t i = (size_t)blockIdx.x * blockDim.x + threadIdx.x; i < total; i += stride) {
        const float* src; __nv_bfloat16 *hi, *lo; size_t j;
        if (i < n1)           { src = wg; hi = g_wg_hi; lo = g_wg_lo; j = i; }
        else if (i < 2 * n1)  { src = wu; hi = g_wu_hi; lo = g_wu_lo; j = i - n1; }
        else                  { src = wd; hi = g_wd_hi; lo = g_wd_lo; j = i - 2 * n1; }
        float w = src[j];
        __nv_bfloat16 h = __float2bfloat16_rn(w);
        float r = w - __bfloat162float(h);
        hi[j] = h;
        lo[j] = __float2bfloat16_rn(r);
    }
}

// ---------------------------------------------------------------------------
// Block max-reduce helper
// ---------------------------------------------------------------------------
__device__ __forceinline__ float block_max(float v, float* red) {
    #pragma unroll
    for (int o = 16; o; o >>= 1) v = fmaxf(v, __shfl_xor_sync(0xFFFFFFFFu, v, o));
    if ((threadIdx.x & 31) == 0) red[threadIdx.x >> 5] = v;
    __syncthreads();
    if (threadIdx.x < 32) {
        float w = (threadIdx.x < (blockDim.x >> 5)) ? red[threadIdx.x] : 0.f;
        #pragma unroll
        for (int o = 16; o; o >>= 1) w = fmaxf(w, __shfl_xor_sync(0xFFFFFFFFu, w, o));
        if (threadIdx.x == 0) red[0] = w;
    }
    __syncthreads();
    return red[0];
}

// ---------------------------------------------------------------------------
// 2) Per-token fake-quant of x: q = clip(rint(x/scale), -128, 127), store q (bf16)
// ---------------------------------------------------------------------------
__global__ void quant_x_kernel(const float* __restrict__ x) {
    __shared__ float red[32];
    const int t = blockIdx.x;
    const float* xr = x + (size_t)t * HDIM;
    float amax = 0.f;
    for (int i = threadIdx.x; i < HDIM; i += blockDim.x)
        amax = fmaxf(amax, fabsf(xr[i]));
    amax = block_max(amax, red);
    float scale = fmaxf(amax * (1.0f / 127.0f), 1e-8f);
    if (threadIdx.x == 0) g_xscale[t] = scale;
    for (int i = threadIdx.x; i < HDIM; i += blockDim.x) {
        float q = rintf(xr[i] / scale);
        q = fminf(fmaxf(q, -128.f), 127.f);
        g_xq[(size_t)t * HDIM + i] = __float2bfloat16_rn(q);
    }
}

// ---------------------------------------------------------------------------
// 3) Fused SwiGLU + per-token fake-quant of inter (row held in SMEM)
// ---------------------------------------------------------------------------
__global__ void swiglu_quant_kernel() {
    extern __shared__ float sinter[];     // IDIM floats = 57344 B
    __shared__ float red[32];
    const int t = blockIdx.x;
    const float* g = g_gate + (size_t)t * IDIM;
    const float* u = g_up   + (size_t)t * IDIM;
    float amax = 0.f;
    for (int i = threadIdx.x; i < IDIM; i += blockDim.x) {
        float gv = g[i];
        float val = (gv / (1.f + expf(-gv))) * u[i];   // silu(g) * u
        sinter[i] = val;
        amax = fmaxf(amax, fabsf(val));
    }
    __syncthreads();
    amax = block_max(amax, red);
    float scale = fmaxf(amax * (1.0f / 127.0f), 1e-8f);
    if (threadIdx.x == 0) g_s2[t] = scale;
    for (int i = threadIdx.x; i < IDIM; i += blockDim.x) {
        float q = rintf(sinter[i] / scale);
        q = fminf(fmaxf(q, -128.f), 127.f);
        g_q2[(size_t)t * IDIM + i] = __float2bfloat16_rn(q);
    }
}

// ---------------------------------------------------------------------------
// 4) NT GEMM: C[M,N] = rowscale[m] * ( A[M,K] * (Bhi+Blo)[N,K]^T )
//    bf16 inputs, fp32 accumulate; A holds exact integers, Bhi/Blo is the split.
//    128x128x32 tile, 3-stage cp.async pipeline, 8 warps (4m x 2n), warp 32x64.
// ---------------------------------------------------------------------------
#define BM 128
#define BN 128
#define BK 32
#define SSTAGE 3
#define SA_STRIDE 40            // BK + 8 pad -> conflict-free LDS
#define TILE_ELEMS (128 * SA_STRIDE)

__global__ void __launch_bounds__(256, 1)
gemm_split_kernel(const __nv_bfloat16* __restrict__ A,
                  const __nv_bfloat16* __restrict__ Bh,
                  const __nv_bfloat16* __restrict__ Bl,
                  const float* __restrict__ rowscale,
                  float* __restrict__ C,
                  int Kdim, int Ndim) {
    extern __shared__ __nv_bfloat16 smem[];
    __nv_bfloat16* sA  = smem;
    __nv_bfloat16* sBh = sA  + SSTAGE * TILE_ELEMS;
    __nv_bfloat16* sBl = sBh + SSTAGE * TILE_ELEMS;

    const int tid  = threadIdx.x;
    const int warp = tid >> 5;
    const int lane = tid & 31;
    const int wm = warp & 3;          // 4 warps over M
    const int wn = warp >> 2;         // 2 warps over N
    const int bm = blockIdx.y * BM;
    const int bn = blockIdx.x * BN;

    const int ar = lane >> 2;         // groupID
    const int ac = (lane & 3) * 2;    // threadInGroup*2

    float acc[2][8][4];
    #pragma unroll
    for (int a = 0; a < 2; a++)
        #pragma unroll
        for (int b = 0; b < 8; b++)
            #pragma unroll
            for (int c = 0; c < 4; c++) acc[a][b][c] = 0.f;

    const int KT = Kdim / BK;

    // stage loader: 512 16B chunks per matrix, 2 per thread
    auto load_stage = [&](int kt, int s) {
        const int k0 = kt * BK;
        #pragma unroll
        for (int j = 0; j < 2; j++) {
            int chunk = tid + j * 256;
            int row = chunk >> 2;
            int cc  = (chunk & 3) * 8;       // element offset within row
            int soff = s * TILE_ELEMS + row * SA_STRIDE + cc;
            cp_async16(&sA [soff], A  + (size_t)(bm + row) * Kdim + k0 + cc);
            cp_async16(&sBh[soff], Bh + (size_t)(bn + row) * Kdim + k0 + cc);
            cp_async16(&sBl[soff], Bl + (size_t)(bn + row) * Kdim + k0 + cc);
        }
    };

    #pragma unroll
    for (int s = 0; s < SSTAGE - 1; s++) { load_stage(s, s); cp_commit(); }

    for (int kt = 0; kt < KT; kt++) {
        cp_wait<SSTAGE - 2>();
        __syncthreads();
        int pre = kt + SSTAGE - 1;
        if (pre < KT) load_stage(pre, pre % SSTAGE);
        cp_commit();

        const __nv_bfloat16* tA  = sA  + (kt % SSTAGE) * TILE_ELEMS;
        const __nv_bfloat16* tBh = sBh + (kt % SSTAGE) * TILE_ELEMS;
        const __nv_bfloat16* tBl = sBl + (kt % SSTAGE) * TILE_ELEMS;

        #pragma unroll
        for (int kk = 0; kk < BK; kk += 16) {
            uint32_t afr[2][4];
            #pragma unroll
            for (int mi = 0; mi < 2; mi++) {
                int r = wm * 32 + mi * 16;
                afr[mi][0] = *(const uint32_t*)&tA[(r + ar    ) * SA_STRIDE + kk + ac    ];
                afr[mi][1] = *(const uint32_t*)&tA[(r + ar + 8) * SA_STRIDE + kk + ac    ];
                afr[mi][2] = *(const uint32_t*)&tA[(r + ar    ) * SA_STRIDE + kk + ac + 8];
                afr[mi][3] = *(const uint32_t*)&tA[(r + ar + 8) * SA_STRIDE + kk + ac + 8];
            }
            #pragma unroll
            for (int ni = 0; ni < 8; ni++) {
                int n = wn * 64 + ni * 8 + ar;
                uint32_t bh0 = *(const uint32_t*)&tBh[n * SA_STRIDE + kk + ac    ];
                uint32_t bh1 = *(const uint32_t*)&tBh[n * SA_STRIDE + kk + ac + 8];
                uint32_t bl0 = *(const uint32_t*)&tBl[n * SA_STRIDE + kk + ac    ];
                uint32_t bl1 = *(const uint32_t*)&tBl[n * SA_STRIDE + kk + ac + 8];
                mma16816(acc[0][ni], afr[0], bh0, bh1);
                mma16816(acc[1][ni], afr[1], bh0, bh1);
                mma16816(acc[0][ni], afr[0], bl0, bl1);
                mma16816(acc[1][ni], afr[1], bl0, bl1);
            }
        }
    }

    // Epilogue: scale by per-token scale, store fp32
    #pragma unroll
    for (int mi = 0; mi < 2; mi++) {
        int r0 = bm + wm * 32 + mi * 16 + ar;
        float s0 = rowscale[r0];
        float s1 = rowscale[r0 + 8];
        #pragma unroll
        for (int ni = 0; ni < 8; ni++) {
            int col = bn + wn * 64 + ni * 8 + ac;
            float2 v0 = make_float2(acc[mi][ni][0] * s0, acc[mi][ni][1] * s0);
            float2 v1 = make_float2(acc[mi][ni][2] * s1, acc[mi][ni][3] * s1);
            *(float2*)&C[(size_t)r0       * Ndim + col] = v0;
            *(float2*)&C[(size_t)(r0 + 8) * Ndim + col] = v1;
        }
    }
}

// ---------------------------------------------------------------------------
// Host launcher
// ---------------------------------------------------------------------------
extern "C" void kernel_launch(void* const* d_in, const int* in_sizes, int n_in,
                              void* d_out, int out_size) {
    const float* x  = (const float*)d_in[0];
    const float* wg = (const float*)d_in[1];
    const float* wu = (const float*)d_in[2];
    const float* wd = (const float*)d_in[3];
    float* out = (float*)d_out;
    (void)in_sizes; (void)n_in; (void)out_size;

    // Device addresses of scratch globals (pure lookup, capture-safe)
    void *p_xq, *p_xs, *p_gate, *p_up, *p_q2, *p_s2;
    void *p_wgh, *p_wgl, *p_wuh, *p_wul, *p_wdh, *p_wdl;
    cudaGetSymbolAddress(&p_xq, g_xq);      cudaGetSymbolAddress(&p_xs, g_xscale);
    cudaGetSymbolAddress(&p_gate, g_gate);  cudaGetSymbolAddress(&p_up, g_up);
    cudaGetSymbolAddress(&p_q2, g_q2);      cudaGetSymbolAddress(&p_s2, g_s2);
    cudaGetSymbolAddress(&p_wgh, g_wg_hi);  cudaGetSymbolAddress(&p_wgl, g_wg_lo);
    cudaGetSymbolAddress(&p_wuh, g_wu_hi);  cudaGetSymbolAddress(&p_wul, g_wu_lo);
    cudaGetSymbolAddress(&p_wdh, g_wd_hi);  cudaGetSymbolAddress(&p_wdl, g_wd_lo);

    const int gemm_smem = SSTAGE * TILE_ELEMS * 3 * (int)sizeof(__nv_bfloat16); // 92160
    const int swig_smem = IDIM * (int)sizeof(float);                            // 57344
    cudaFuncSetAttribute(gemm_split_kernel,
                         cudaFuncAttributeMaxDynamicSharedMemorySize, gemm_smem);
    cudaFuncSetAttribute(swiglu_quant_kernel,
                         cudaFuncAttributeMaxDynamicSharedMemorySize, swig_smem);

    // 1) split weights fp32 -> bf16 hi/lo
    split_w_kernel<<<2048, 256>>>(wg, wu, wd);

    // 2) per-token fake-quant of x
    quant_x_kernel<<<M_TOK, 256>>>(x);

    // 3) gate = xscale * (q . Wg^T), up = xscale * (q . Wu^T)
    dim3 grid1(IDIM / BN, M_TOK / BM);   // (112, 32)
    gemm_split_kernel<<<grid1, 256, gemm_smem>>>(
        (const __nv_bfloat16*)p_xq, (const __nv_bfloat16*)p_wgh, (const __nv_bfloat16*)p_wgl,
        (const float*)p_xs, (float*)p_gate, HDIM, IDIM);
    gemm_split_kernel<<<grid1, 256, gemm_smem>>>(
        (const __nv_bfloat16*)p_xq, (const __nv_bfloat16*)p_wuh, (const __nv_bfloat16*)p_wul,
        (const float*)p_xs, (float*)p_up, HDIM, IDIM);

    // 4) inter = silu(gate)*up, fake-quant per token
    swiglu_quant_kernel<<<M_TOK, 512, swig_smem>>>();

    // 5) out = s2 * (q2 . Wd^T)
    dim3 grid3(HDIM / BN, M_TOK / BM);   // (32, 32)
    gemm_split_kernel<<<grid3, 256, gemm_smem>>>(
        (const __nv_bfloat16*)p_q2, (const __nv_bfloat16*)p_wdh, (const __nv_bfloat16*)p_wdl,
        (const float*)p_s2, out, IDIM, HDIM);
}

// round 7
// speedup vs baseline: 1.5754x; 1.5754x over previous
#include <cuda_runtime.h>
#include <cuda_bf16.h>
#include <cstdint>

// Problem dims (fixed by the dataset)
#define M_TOK 4096            // B*S
#define HDIM  4096
#define IDIM  14336

// ---------------------------------------------------------------------------
// Device scratch (allocation-free rule: __device__ globals)
// ---------------------------------------------------------------------------
__device__ __nv_bfloat16 g_xq[(size_t)M_TOK * HDIM];      // quantized x (ints in bf16)
__device__ float         g_xscale[M_TOK];
__device__ float         g_inter[(size_t)M_TOK * IDIM];   // silu(gate)*up, fp32
__device__ __nv_bfloat16 g_q2[(size_t)M_TOK * IDIM];      // quantized inter
__device__ float         g_s2[M_TOK];
__device__ __nv_bfloat16 g_wg_hi[(size_t)IDIM * HDIM];
__device__ __nv_bfloat16 g_wg_lo[(size_t)IDIM * HDIM];
__device__ __nv_bfloat16 g_wu_hi[(size_t)IDIM * HDIM];
__device__ __nv_bfloat16 g_wu_lo[(size_t)IDIM * HDIM];
__device__ __nv_bfloat16 g_wd_hi[(size_t)HDIM * IDIM];
__device__ __nv_bfloat16 g_wd_lo[(size_t)HDIM * IDIM];

// ---------------------------------------------------------------------------
// PTX helpers (all legal at compute_103 base target)
// ---------------------------------------------------------------------------
__device__ __forceinline__ uint32_t smem_u32(const void* p) {
    uint32_t a;
    asm("{ .reg .u64 t; cvta.to.shared.u64 t, %1; cvt.u32.u64 %0, t; }" : "=r"(a) : "l"(p));
    return a;
}
__device__ __forceinline__ void cp_async16(uint32_t saddr, const void* g) {
    asm volatile("cp.async.cg.shared.global [%0], [%1], 16;\n" :: "r"(saddr), "l"(g));
}
__device__ __forceinline__ void cp_commit() { asm volatile("cp.async.commit_group;\n"); }
template<int N> __device__ __forceinline__ void cp_wait() {
    asm volatile("cp.async.wait_group %0;\n" :: "n"(N));
}
__device__ __forceinline__ void ldsm_x4(uint32_t* r, uint32_t addr) {
    asm volatile("ldmatrix.sync.aligned.m8n8.x4.shared.b16 {%0,%1,%2,%3}, [%4];"
                 : "=r"(r[0]), "=r"(r[1]), "=r"(r[2]), "=r"(r[3]) : "r"(addr));
}
__device__ __forceinline__ void mma16816(float* c, const uint32_t* a, uint32_t b0, uint32_t b1) {
    asm volatile(
        "mma.sync.aligned.m16n8k16.row.col.f32.bf16.bf16.f32 "
        "{%0,%1,%2,%3},{%4,%5,%6,%7},{%8,%9},{%0,%1,%2,%3};\n"
        : "+f"(c[0]), "+f"(c[1]), "+f"(c[2]), "+f"(c[3])
        : "r"(a[0]), "r"(a[1]), "r"(a[2]), "r"(a[3]), "r"(b0), "r"(b1));
}

// ---------------------------------------------------------------------------
// Templated NT GEMM, BM=128 x BN=128 x BK=64, 8 warps (4m x 2n), warp 32x64.
// NMAT B-matrices share the A tile; pairs (2i,2i+1) = (hi,lo) accumulate into
// accumulator i. SWIGLU epilogue: C = silu(xs*accG)*(xs*accU); else C = s*acc.
// SMEM: XOR-swizzled 128B rows; loads via cp.async, frags via ldmatrix.x4.
// ---------------------------------------------------------------------------
template<int NMAT, bool SWIGLU>
__global__ void __launch_bounds__(256, 1)
hgemm_kernel(const __nv_bfloat16* __restrict__ A,
             const __nv_bfloat16* __restrict__ B0,
             const __nv_bfloat16* __restrict__ B1,
             const __nv_bfloat16* __restrict__ B2,
             const __nv_bfloat16* __restrict__ B3,
             const float* __restrict__ rowscale,
             float* __restrict__ Cout,
             int K, int N)
{
    constexpr int TILE  = 16384;                 // 128 rows * 128B
    constexpr int STAGE = (1 + NMAT) * TILE;     // A + NMAT B tiles
    constexpr int NACC  = NMAT / 2;

    extern __shared__ char smem_raw[];
    const uint32_t sb = (smem_u32(smem_raw) + 127u) & ~127u;

    const int tid  = threadIdx.x;
    const int warp = tid >> 5;
    const int lane = tid & 31;
    const int wm = warp & 3;
    const int wn = warp >> 2;
    const int bm = blockIdx.x * 128;
    const int bn = blockIdx.y * 128;

    const __nv_bfloat16* Bs[4] = {B0, B1, B2, B3};

    float acc[NACC][2][8][4];
    #pragma unroll
    for (int q = 0; q < NACC; q++)
        #pragma unroll
        for (int a = 0; a < 2; a++)
            #pragma unroll
            for (int b = 0; b < 8; b++)
                #pragma unroll
                for (int c = 0; c < 4; c++) acc[q][a][b][c] = 0.f;

    const int KT = K >> 6;   // BK=64

    // per-stage loader: (1+NMAT)*1024 16B chunks, 4*(1+NMAT) per thread
    auto load_stage = [&](int kt, int s) {
        const int k0 = kt * 64;
        #pragma unroll
        for (int i = 0; i < 4; i++) {
            int id  = tid + i * 256;       // 0..1023
            int row = id >> 3, c = id & 7;
            uint32_t dst = sb + s * STAGE + row * 128 + (((c ^ (row & 7)) << 4));
            cp_async16(dst, A + (size_t)(bm + row) * K + k0 + c * 8);
        }
        #pragma unroll
        for (int m = 0; m < NMAT; m++) {
            #pragma unroll
            for (int i = 0; i < 4; i++) {
                int id  = tid + i * 256;
                int row = id >> 3, c = id & 7;
                uint32_t dst = sb + s * STAGE + (1 + m) * TILE + row * 128
                             + (((c ^ (row & 7)) << 4));
                cp_async16(dst, Bs[m] + (size_t)(bn + row) * K + k0 + c * 8);
            }
        }
    };

    // fragment row offsets (row & 7 == lane & 7 for all frags)
    const int la7 = lane & 7;
    uint32_t a_row[2], b_row[4];
    #pragma unroll
    for (int mi = 0; mi < 2; mi++)
        a_row[mi] = (uint32_t)(wm * 32 + mi * 16 + la7 + ((lane >> 3) & 1) * 8) * 128;
    #pragma unroll
    for (int p = 0; p < 4; p++)
        b_row[p] = (uint32_t)(wn * 64 + p * 16 + la7 + (lane >> 4) * 8) * 128 ;
    const int kca = (lane >> 4);        // A k-chunk select
    const int kcb = ((lane >> 3) & 1);  // B k-chunk select

    load_stage(0, 0);
    cp_commit();

    for (int kt = 0; kt < KT; kt++) {
        cp_wait<0>();
        __syncthreads();
        if (kt + 1 < KT) load_stage(kt + 1, (kt + 1) & 1);
        cp_commit();

        const uint32_t base = sb + (kt & 1) * STAGE;
        #pragma unroll
        for (int kk = 0; kk < 4; kk++) {
            const uint32_t offa = (uint32_t)(((kk * 2 + kca) ^ la7) << 4);
            const uint32_t offb = (uint32_t)(((kk * 2 + kcb) ^ la7) << 4);
            uint32_t afr[2][4];
            ldsm_x4(afr[0], base + a_row[0] + offa);
            ldsm_x4(afr[1], base + a_row[1] + offa);
            #pragma unroll
            for (int p = 0; p < 4; p++) {
                #pragma unroll
                for (int m = 0; m < NMAT; m++) {
                    uint32_t bfr[4];
                    ldsm_x4(bfr, base + (1 + m) * TILE + b_row[p] + offb);
                    float* c0 = acc[m >> 1][0][2 * p];
                    float* c1 = acc[m >> 1][1][2 * p];
                    float* c2 = acc[m >> 1][0][2 * p + 1];
                    float* c3 = acc[m >> 1][1][2 * p + 1];
                    mma16816(c0, afr[0], bfr[0], bfr[1]);
                    mma16816(c1, afr[1], bfr[0], bfr[1]);
                    mma16816(c2, afr[0], bfr[2], bfr[3]);
                    mma16816(c3, afr[1], bfr[2], bfr[3]);
                }
            }
        }
    }

    // epilogue
    #pragma unroll
    for (int mi = 0; mi < 2; mi++) {
        const int r0 = bm + wm * 32 + mi * 16 + (lane >> 2);
        const float s0 = rowscale[r0];
        const float s1 = rowscale[r0 + 8];
        #pragma unroll
        for (int ni = 0; ni < 8; ni++) {
            const int col = bn + wn * 64 + ni * 8 + (lane & 3) * 2;
            if (SWIGLU) {
                float g0 = acc[0][mi][ni][0] * s0, g1 = acc[0][mi][ni][1] * s0;
                float u0 = acc[1][mi][ni][0] * s0, u1 = acc[1][mi][ni][1] * s0;
                float v0 = __fdividef(g0, 1.f + expf(-g0)) * u0;
                float v1 = __fdividef(g1, 1.f + expf(-g1)) * u1;
                *(float2*)&Cout[(size_t)r0 * N + col] = make_float2(v0, v1);
                float g2 = acc[0][mi][ni][2] * s1, g3 = acc[0][mi][ni][3] * s1;
                float u2 = acc[1][mi][ni][2] * s1, u3 = acc[1][mi][ni][3] * s1;
                float v2 = __fdividef(g2, 1.f + expf(-g2)) * u2;
                float v3 = __fdividef(g3, 1.f + expf(-g3)) * u3;
                *(float2*)&Cout[(size_t)(r0 + 8) * N + col] = make_float2(v2, v3);
            } else {
                *(float2*)&Cout[(size_t)r0 * N + col] =
                    make_float2(acc[0][mi][ni][0] * s0, acc[0][mi][ni][1] * s0);
                *(float2*)&Cout[(size_t)(r0 + 8) * N + col] =
                    make_float2(acc[0][mi][ni][2] * s1, acc[0][mi][ni][3] * s1);
            }
        }
    }
}

// ---------------------------------------------------------------------------
// Weight split fp32 -> bf16 hi/lo (vectorized)
// ---------------------------------------------------------------------------
__global__ void split_one_kernel(const float4* __restrict__ src,
                                 __nv_bfloat162* __restrict__ hi,
                                 __nv_bfloat162* __restrict__ lo, int n4) {
    const int stride = gridDim.x * blockDim.x;
    for (int i = blockIdx.x * blockDim.x + threadIdx.x; i < n4; i += stride) {
        float4 w = src[i];
        __nv_bfloat16 hx = __float2bfloat16_rn(w.x);
        __nv_bfloat16 hy = __float2bfloat16_rn(w.y);
        __nv_bfloat16 hz = __float2bfloat16_rn(w.z);
        __nv_bfloat16 hw = __float2bfloat16_rn(w.w);
        hi[2*i]   = __halves2bfloat162(hx, hy);
        hi[2*i+1] = __halves2bfloat162(hz, hw);
        lo[2*i]   = __halves2bfloat162(__float2bfloat16_rn(w.x - __bfloat162float(hx)),
                                       __float2bfloat16_rn(w.y - __bfloat162float(hy)));
        lo[2*i+1] = __halves2bfloat162(__float2bfloat16_rn(w.z - __bfloat162float(hz)),
                                       __float2bfloat16_rn(w.w - __bfloat162float(hw)));
    }
}

// ---------------------------------------------------------------------------
// Block max-reduce
// ---------------------------------------------------------------------------
__device__ __forceinline__ float block_max(float v, float* red) {
    #pragma unroll
    for (int o = 16; o; o >>= 1) v = fmaxf(v, __shfl_xor_sync(0xFFFFFFFFu, v, o));
    if ((threadIdx.x & 31) == 0) red[threadIdx.x >> 5] = v;
    __syncthreads();
    if (threadIdx.x < 32) {
        float w = (threadIdx.x < (blockDim.x >> 5)) ? red[threadIdx.x] : 0.f;
        #pragma unroll
        for (int o = 16; o; o >>= 1) w = fmaxf(w, __shfl_xor_sync(0xFFFFFFFFu, w, o));
        if (threadIdx.x == 0) red[0] = w;
    }
    __syncthreads();
    return red[0];
}

// ---------------------------------------------------------------------------
// Per-token fake-quant of x (row cached in smem)
// ---------------------------------------------------------------------------
__global__ void quant_x_kernel(const float* __restrict__ x) {
    __shared__ float red[32];
    __shared__ float row[HDIM];
    const int t = blockIdx.x;
    const float4* xr = (const float4*)(x + (size_t)t * HDIM);
    float amax = 0.f;
    for (int i = threadIdx.x; i < HDIM / 4; i += blockDim.x) {
        float4 v = xr[i];
        ((float4*)row)[i] = v;
        amax = fmaxf(amax, fmaxf(fmaxf(fabsf(v.x), fabsf(v.y)), fmaxf(fabsf(v.z), fabsf(v.w))));
    }
    __syncthreads();
    amax = block_max(amax, red);
    const float scale = fmaxf(amax * (1.0f / 127.0f), 1e-8f);
    if (threadIdx.x == 0) g_xscale[t] = scale;
    const float inv = 1.0f / scale;
    for (int i = threadIdx.x; i < HDIM; i += blockDim.x) {
        float q = rintf(row[i] * inv);
        q = fminf(fmaxf(q, -128.f), 127.f);
        g_xq[(size_t)t * HDIM + i] = __float2bfloat16_rn(q);
    }
}

// ---------------------------------------------------------------------------
// Per-token fake-quant of inter (inter already holds silu(gate)*up)
// ---------------------------------------------------------------------------
__global__ void quant2_kernel() {
    extern __shared__ float srow[];    // IDIM floats
    __shared__ float red[32];
    const int t = blockIdx.x;
    const float4* ir = (const float4*)(g_inter + (size_t)t * IDIM);
    float amax = 0.f;
    for (int i = threadIdx.x; i < IDIM / 4; i += blockDim.x) {
        float4 v = ir[i];
        ((float4*)srow)[i] = v;
        amax = fmaxf(amax, fmaxf(fmaxf(fabsf(v.x), fabsf(v.y)), fmaxf(fabsf(v.z), fabsf(v.w))));
    }
    __syncthreads();
    amax = block_max(amax, red);
    const float scale = fmaxf(amax * (1.0f / 127.0f), 1e-8f);
    if (threadIdx.x == 0) g_s2[t] = scale;
    const float inv = 1.0f / scale;
    for (int i = threadIdx.x; i < IDIM; i += blockDim.x) {
        float q = rintf(srow[i] * inv);
        q = fminf(fmaxf(q, -128.f), 127.f);
        g_q2[(size_t)t * IDIM + i] = __float2bfloat16_rn(q);
    }
}

// ---------------------------------------------------------------------------
// Host launcher
// ---------------------------------------------------------------------------
extern "C" void kernel_launch(void* const* d_in, const int* in_sizes, int n_in,
                              void* d_out, int out_size) {
    const float* x  = (const float*)d_in[0];
    const float* wg = (const float*)d_in[1];
    const float* wu = (const float*)d_in[2];
    const float* wd = (const float*)d_in[3];
    float* out = (float*)d_out;
    (void)in_sizes; (void)n_in; (void)out_size;

    void *p_xq, *p_xs, *p_inter, *p_q2, *p_s2;
    void *p_wgh, *p_wgl, *p_wuh, *p_wul, *p_wdh, *p_wdl;
    cudaGetSymbolAddress(&p_xq, g_xq);      cudaGetSymbolAddress(&p_xs, g_xscale);
    cudaGetSymbolAddress(&p_inter, g_inter);
    cudaGetSymbolAddress(&p_q2, g_q2);      cudaGetSymbolAddress(&p_s2, g_s2);
    cudaGetSymbolAddress(&p_wgh, g_wg_hi);  cudaGetSymbolAddress(&p_wgl, g_wg_lo);
    cudaGetSymbolAddress(&p_wuh, g_wu_hi);  cudaGetSymbolAddress(&p_wul, g_wu_lo);
    cudaGetSymbolAddress(&p_wdh, g_wd_hi);  cudaGetSymbolAddress(&p_wdl, g_wd_lo);

    const int smem_fused = 2 * 5 * 16384 + 128;   // 163968
    const int smem_down  = 2 * 3 * 16384 + 128;   // 98432
    const int smem_q2    = IDIM * (int)sizeof(float);
    cudaFuncSetAttribute(hgemm_kernel<4, true>,
                         cudaFuncAttributeMaxDynamicSharedMemorySize, smem_fused);
    cudaFuncSetAttribute(hgemm_kernel<2, false>,
                         cudaFuncAttributeMaxDynamicSharedMemorySize, smem_down);
    cudaFuncSetAttribute(quant2_kernel,
                         cudaFuncAttributeMaxDynamicSharedMemorySize, smem_q2);

    // 1) split weights fp32 -> bf16 hi/lo
    const int n4 = (IDIM / 4) * HDIM;
    split_one_kernel<<<1024, 256>>>((const float4*)wg, (__nv_bfloat162*)p_wgh,
                                    (__nv_bfloat162*)p_wgl, n4);
    split_one_kernel<<<1024, 256>>>((const float4*)wu, (__nv_bfloat162*)p_wuh,
                                    (__nv_bfloat162*)p_wul, n4);
    split_one_kernel<<<1024, 256>>>((const float4*)wd, (__nv_bfloat162*)p_wdh,
                                    (__nv_bfloat162*)p_wdl, n4);

    // 2) per-token fake-quant of x
    quant_x_kernel<<<M_TOK, 256>>>(x);

    // 3) fused gate/up GEMM + SwiGLU epilogue -> inter (fp32)
    dim3 g1(M_TOK / 128, IDIM / 128);   // (32, 112), m fastest
    hgemm_kernel<4, true><<<g1, 256, smem_fused>>>(
        (const __nv_bfloat16*)p_xq,
        (const __nv_bfloat16*)p_wgh, (const __nv_bfloat16*)p_wgl,
        (const __nv_bfloat16*)p_wuh, (const __nv_bfloat16*)p_wul,
        (const float*)p_xs, (float*)p_inter, HDIM, IDIM);

    // 4) fake-quant of inter
    quant2_kernel<<<M_TOK, 512, smem_q2>>>();

    // 5) down GEMM -> out
    dim3 g3(M_TOK / 128, HDIM / 128);   // (32, 32)
    hgemm_kernel<2, false><<<g3, 256, smem_down>>>(
        (const __nv_bfloat16*)p_q2,
        (const __nv_bfloat16*)p_wdh, (const __nv_bfloat16*)p_wdl,
        (const __nv_bfloat16*)p_wdh, (const __nv_bfloat16*)p_wdl,
        (const float*)p_s2, out, IDIM, HDIM);
}

// round 8
// speedup vs baseline: 1.5755x; 1.0000x over previous
#include <cuda_runtime.h>
#include <cuda_bf16.h>
#include <cstdint>

// Problem dims (fixed by the dataset)
#define M_TOK 4096            // B*S
#define HDIM  4096
#define IDIM  14336

// ---------------------------------------------------------------------------
// Device scratch (allocation-free rule: __device__ globals)
// ---------------------------------------------------------------------------
__device__ __nv_bfloat16 g_xq[(size_t)M_TOK * HDIM];      // quantized x (ints in bf16)
__device__ float         g_xscale[M_TOK];
__device__ float         g_inter[(size_t)M_TOK * IDIM];   // silu(gate)*up, fp32
__device__ __nv_bfloat16 g_q2[(size_t)M_TOK * IDIM];      // quantized inter
__device__ float         g_s2[M_TOK];
__device__ __nv_bfloat16 g_wg_hi[(size_t)IDIM * HDIM];
__device__ __nv_bfloat16 g_wg_lo[(size_t)IDIM * HDIM];
__device__ __nv_bfloat16 g_wu_hi[(size_t)IDIM * HDIM];
__device__ __nv_bfloat16 g_wu_lo[(size_t)IDIM * HDIM];
__device__ __nv_bfloat16 g_wd_hi[(size_t)HDIM * IDIM];
__device__ __nv_bfloat16 g_wd_lo[(size_t)HDIM * IDIM];

// ---------------------------------------------------------------------------
// PTX helpers (all legal at compute_103 base target)
// ---------------------------------------------------------------------------
__device__ __forceinline__ uint32_t smem_u32(const void* p) {
    uint32_t a;
    asm("{ .reg .u64 t; cvta.to.shared.u64 t, %1; cvt.u32.u64 %0, t; }" : "=r"(a) : "l"(p));
    return a;
}
__device__ __forceinline__ void cp_async16(uint32_t saddr, const void* g) {
    asm volatile("cp.async.cg.shared.global [%0], [%1], 16;\n" :: "r"(saddr), "l"(g));
}
__device__ __forceinline__ void cp_commit() { asm volatile("cp.async.commit_group;\n"); }
template<int N> __device__ __forceinline__ void cp_wait() {
    asm volatile("cp.async.wait_group %0;\n" :: "n"(N));
}
__device__ __forceinline__ void ldsm_x4(uint32_t* r, uint32_t addr) {
    asm volatile("ldmatrix.sync.aligned.m8n8.x4.shared.b16 {%0,%1,%2,%3}, [%4];"
                 : "=r"(r[0]), "=r"(r[1]), "=r"(r[2]), "=r"(r[3]) : "r"(addr));
}
__device__ __forceinline__ void mma16816(float* c, const uint32_t* a, uint32_t b0, uint32_t b1) {
    asm volatile(
        "mma.sync.aligned.m16n8k16.row.col.f32.bf16.bf16.f32 "
        "{%0,%1,%2,%3},{%4,%5,%6,%7},{%8,%9},{%0,%1,%2,%3};\n"
        : "+f"(c[0]), "+f"(c[1]), "+f"(c[2]), "+f"(c[3])
        : "r"(a[0]), "r"(a[1]), "r"(a[2]), "r"(a[3]), "r"(b0), "r"(b1));
}

// ---------------------------------------------------------------------------
// Templated NT GEMM, BM=128 x BN=128 x BK=64, 8 warps (4m x 2n), warp 32x64.
// NMAT B-matrices share the A tile; pairs (2i,2i+1) = (hi,lo) accumulate into
// accumulator i. SWIGLU epilogue: C = silu(xs*accG)*(xs*accU); else C = s*acc.
// SMEM: XOR-swizzled 128B rows; loads via cp.async, frags via ldmatrix.x4.
// ---------------------------------------------------------------------------
template<int NMAT, bool SWIGLU>
__global__ void __launch_bounds__(256, 1)
hgemm_kernel(const __nv_bfloat16* __restrict__ A,
             const __nv_bfloat16* __restrict__ B0,
             const __nv_bfloat16* __restrict__ B1,
             const __nv_bfloat16* __restrict__ B2,
             const __nv_bfloat16* __restrict__ B3,
             const float* __restrict__ rowscale,
             float* __restrict__ Cout,
             int K, int N)
{
    constexpr int TILE  = 16384;                 // 128 rows * 128B
    constexpr int STAGE = (1 + NMAT) * TILE;     // A + NMAT B tiles
    constexpr int NACC  = NMAT / 2;

    extern __shared__ char smem_raw[];
    const uint32_t sb = (smem_u32(smem_raw) + 127u) & ~127u;

    const int tid  = threadIdx.x;
    const int warp = tid >> 5;
    const int lane = tid & 31;
    const int wm = warp & 3;
    const int wn = warp >> 2;
    const int bm = blockIdx.x * 128;
    const int bn = blockIdx.y * 128;

    const __nv_bfloat16* Bs[4] = {B0, B1, B2, B3};

    float acc[NACC][2][8][4];
    #pragma unroll
    for (int q = 0; q < NACC; q++)
        #pragma unroll
        for (int a = 0; a < 2; a++)
            #pragma unroll
            for (int b = 0; b < 8; b++)
                #pragma unroll
                for (int c = 0; c < 4; c++) acc[q][a][b][c] = 0.f;

    const int KT = K >> 6;   // BK=64

    // per-stage loader: (1+NMAT)*1024 16B chunks, 4*(1+NMAT) per thread
    auto load_stage = [&](int kt, int s) {
        const int k0 = kt * 64;
        #pragma unroll
        for (int i = 0; i < 4; i++) {
            int id  = tid + i * 256;       // 0..1023
            int row = id >> 3, c = id & 7;
            uint32_t dst = sb + s * STAGE + row * 128 + (((c ^ (row & 7)) << 4));
            cp_async16(dst, A + (size_t)(bm + row) * K + k0 + c * 8);
        }
        #pragma unroll
        for (int m = 0; m < NMAT; m++) {
            #pragma unroll
            for (int i = 0; i < 4; i++) {
                int id  = tid + i * 256;
                int row = id >> 3, c = id & 7;
                uint32_t dst = sb + s * STAGE + (1 + m) * TILE + row * 128
                             + (((c ^ (row & 7)) << 4));
                cp_async16(dst, Bs[m] + (size_t)(bn + row) * K + k0 + c * 8);
            }
        }
    };

    // fragment row offsets (row & 7 == lane & 7 for all frags)
    const int la7 = lane & 7;
    uint32_t a_row[2], b_row[4];
    #pragma unroll
    for (int mi = 0; mi < 2; mi++)
        a_row[mi] = (uint32_t)(wm * 32 + mi * 16 + la7 + ((lane >> 3) & 1) * 8) * 128;
    #pragma unroll
    for (int p = 0; p < 4; p++)
        b_row[p] = (uint32_t)(wn * 64 + p * 16 + la7 + (lane >> 4) * 8) * 128 ;
    const int kca = (lane >> 4);        // A k-chunk select
    const int kcb = ((lane >> 3) & 1);  // B k-chunk select

    load_stage(0, 0);
    cp_commit();

    for (int kt = 0; kt < KT; kt++) {
        cp_wait<0>();
        __syncthreads();
        if (kt + 1 < KT) load_stage(kt + 1, (kt + 1) & 1);
        cp_commit();

        const uint32_t base = sb + (kt & 1) * STAGE;
        #pragma unroll
        for (int kk = 0; kk < 4; kk++) {
            const uint32_t offa = (uint32_t)(((kk * 2 + kca) ^ la7) << 4);
            const uint32_t offb = (uint32_t)(((kk * 2 + kcb) ^ la7) << 4);
            uint32_t afr[2][4];
            ldsm_x4(afr[0], base + a_row[0] + offa);
            ldsm_x4(afr[1], base + a_row[1] + offa);
            #pragma unroll
            for (int p = 0; p < 4; p++) {
                #pragma unroll
                for (int m = 0; m < NMAT; m++) {
                    uint32_t bfr[4];
                    ldsm_x4(bfr, base + (1 + m) * TILE + b_row[p] + offb);
                    float* c0 = acc[m >> 1][0][2 * p];
                    float* c1 = acc[m >> 1][1][2 * p];
                    float* c2 = acc[m >> 1][0][2 * p + 1];
                    float* c3 = acc[m >> 1][1][2 * p + 1];
                    mma16816(c0, afr[0], bfr[0], bfr[1]);
                    mma16816(c1, afr[1], bfr[0], bfr[1]);
                    mma16816(c2, afr[0], bfr[2], bfr[3]);
                    mma16816(c3, afr[1], bfr[2], bfr[3]);
                }
            }
        }
    }

    // epilogue
    #pragma unroll
    for (int mi = 0; mi < 2; mi++) {
        const int r0 = bm + wm * 32 + mi * 16 + (lane >> 2);
        const float s0 = rowscale[r0];
        const float s1 = rowscale[r0 + 8];
        #pragma unroll
        for (int ni = 0; ni < 8; ni++) {
            const int col = bn + wn * 64 + ni * 8 + (lane & 3) * 2;
            if (SWIGLU) {
                float g0 = acc[0][mi][ni][0] * s0, g1 = acc[0][mi][ni][1] * s0;
                float u0 = acc[1][mi][ni][0] * s0, u1 = acc[1][mi][ni][1] * s0;
                float v0 = __fdividef(g0, 1.f + expf(-g0)) * u0;
                float v1 = __fdividef(g1, 1.f + expf(-g1)) * u1;
                *(float2*)&Cout[(size_t)r0 * N + col] = make_float2(v0, v1);
                float g2 = acc[0][mi][ni][2] * s1, g3 = acc[0][mi][ni][3] * s1;
                float u2 = acc[1][mi][ni][2] * s1, u3 = acc[1][mi][ni][3] * s1;
                float v2 = __fdividef(g2, 1.f + expf(-g2)) * u2;
                float v3 = __fdividef(g3, 1.f + expf(-g3)) * u3;
                *(float2*)&Cout[(size_t)(r0 + 8) * N + col] = make_float2(v2, v3);
            } else {
                *(float2*)&Cout[(size_t)r0 * N + col] =
                    make_float2(acc[0][mi][ni][0] * s0, acc[0][mi][ni][1] * s0);
                *(float2*)&Cout[(size_t)(r0 + 8) * N + col] =
                    make_float2(acc[0][mi][ni][2] * s1, acc[0][mi][ni][3] * s1);
            }
        }
    }
}

// ---------------------------------------------------------------------------
// Weight split fp32 -> bf16 hi/lo (vectorized)
// ---------------------------------------------------------------------------
__global__ void split_one_kernel(const float4* __restrict__ src,
                                 __nv_bfloat162* __restrict__ hi,
                                 __nv_bfloat162* __restrict__ lo, int n4) {
    const int stride = gridDim.x * blockDim.x;
    for (int i = blockIdx.x * blockDim.x + threadIdx.x; i < n4; i += stride) {
        float4 w = src[i];
        __nv_bfloat16 hx = __float2bfloat16_rn(w.x);
        __nv_bfloat16 hy = __float2bfloat16_rn(w.y);
        __nv_bfloat16 hz = __float2bfloat16_rn(w.z);
        __nv_bfloat16 hw = __float2bfloat16_rn(w.w);
        hi[2*i]   = __halves2bfloat162(hx, hy);
        hi[2*i+1] = __halves2bfloat162(hz, hw);
        lo[2*i]   = __halves2bfloat162(__float2bfloat16_rn(w.x - __bfloat162float(hx)),
                                       __float2bfloat16_rn(w.y - __bfloat162float(hy)));
        lo[2*i+1] = __halves2bfloat162(__float2bfloat16_rn(w.z - __bfloat162float(hz)),
                                       __float2bfloat16_rn(w.w - __bfloat162float(hw)));
    }
}

// ---------------------------------------------------------------------------
// Block max-reduce
// ---------------------------------------------------------------------------
__device__ __forceinline__ float block_max(float v, float* red) {
    #pragma unroll
    for (int o = 16; o; o >>= 1) v = fmaxf(v, __shfl_xor_sync(0xFFFFFFFFu, v, o));
    if ((threadIdx.x & 31) == 0) red[threadIdx.x >> 5] = v;
    __syncthreads();
    if (threadIdx.x < 32) {
        float w = (threadIdx.x < (blockDim.x >> 5)) ? red[threadIdx.x] : 0.f;
        #pragma unroll
        for (int o = 16; o; o >>= 1) w = fmaxf(w, __shfl_xor_sync(0xFFFFFFFFu, w, o));
        if (threadIdx.x == 0) red[0] = w;
    }
    __syncthreads();
    return red[0];
}

// ---------------------------------------------------------------------------
// Per-token fake-quant of x (row cached in smem)
// ---------------------------------------------------------------------------
__global__ void quant_x_kernel(const float* __restrict__ x) {
    __shared__ float red[32];
    __shared__ float row[HDIM];
    const int t = blockIdx.x;
    const float4* xr = (const float4*)(x + (size_t)t * HDIM);
    float amax = 0.f;
    for (int i = threadIdx.x; i < HDIM / 4; i += blockDim.x) {
        float4 v = xr[i];
        ((float4*)row)[i] = v;
        amax = fmaxf(amax, fmaxf(fmaxf(fabsf(v.x), fabsf(v.y)), fmaxf(fabsf(v.z), fabsf(v.w))));
    }
    __syncthreads();
    amax = block_max(amax, red);
    const float scale = fmaxf(amax * (1.0f / 127.0f), 1e-8f);
    if (threadIdx.x == 0) g_xscale[t] = scale;
    const float inv = 1.0f / scale;
    for (int i = threadIdx.x; i < HDIM; i += blockDim.x) {
        float q = rintf(row[i] * inv);
        q = fminf(fmaxf(q, -128.f), 127.f);
        g_xq[(size_t)t * HDIM + i] = __float2bfloat16_rn(q);
    }
}

// ---------------------------------------------------------------------------
// Per-token fake-quant of inter (inter already holds silu(gate)*up)
// ---------------------------------------------------------------------------
__global__ void quant2_kernel() {
    extern __shared__ float srow[];    // IDIM floats
    __shared__ float red[32];
    const int t = blockIdx.x;
    const float4* ir = (const float4*)(g_inter + (size_t)t * IDIM);
    float amax = 0.f;
    for (int i = threadIdx.x; i < IDIM / 4; i += blockDim.x) {
        float4 v = ir[i];
        ((float4*)srow)[i] = v;
        amax = fmaxf(amax, fmaxf(fmaxf(fabsf(v.x), fabsf(v.y)), fmaxf(fabsf(v.z), fabsf(v.w))));
    }
    __syncthreads();
    amax = block_max(amax, red);
    const float scale = fmaxf(amax * (1.0f / 127.0f), 1e-8f);
    if (threadIdx.x == 0) g_s2[t] = scale;
    const float inv = 1.0f / scale;
    for (int i = threadIdx.x; i < IDIM; i += blockDim.x) {
        float q = rintf(srow[i] * inv);
        q = fminf(fmaxf(q, -128.f), 127.f);
        g_q2[(size_t)t * IDIM + i] = __float2bfloat16_rn(q);
    }
}

// ---------------------------------------------------------------------------
// Host launcher
// ---------------------------------------------------------------------------
extern "C" void kernel_launch(void* const* d_in, const int* in_sizes, int n_in,
                              void* d_out, int out_size) {
    const float* x  = (const float*)d_in[0];
    const float* wg = (const float*)d_in[1];
    const float* wu = (const float*)d_in[2];
    const float* wd = (const float*)d_in[3];
    float* out = (float*)d_out;
    (void)in_sizes; (void)n_in; (void)out_size;

    void *p_xq, *p_xs, *p_inter, *p_q2, *p_s2;
    void *p_wgh, *p_wgl, *p_wuh, *p_wul, *p_wdh, *p_wdl;
    cudaGetSymbolAddress(&p_xq, g_xq);      cudaGetSymbolAddress(&p_xs, g_xscale);
    cudaGetSymbolAddress(&p_inter, g_inter);
    cudaGetSymbolAddress(&p_q2, g_q2);      cudaGetSymbolAddress(&p_s2, g_s2);
    cudaGetSymbolAddress(&p_wgh, g_wg_hi);  cudaGetSymbolAddress(&p_wgl, g_wg_lo);
    cudaGetSymbolAddress(&p_wuh, g_wu_hi);  cudaGetSymbolAddress(&p_wul, g_wu_lo);
    cudaGetSymbolAddress(&p_wdh, g_wd_hi);  cudaGetSymbolAddress(&p_wdl, g_wd_lo);

    const int smem_fused = 2 * 5 * 16384 + 128;   // 163968
    const int smem_down  = 2 * 3 * 16384 + 128;   // 98432
    const int smem_q2    = IDIM * (int)sizeof(float);
    cudaFuncSetAttribute(hgemm_kernel<4, true>,
                         cudaFuncAttributeMaxDynamicSharedMemorySize, smem_fused);
    cudaFuncSetAttribute(hgemm_kernel<2, false>,
                         cudaFuncAttributeMaxDynamicSharedMemorySize, smem_down);
    cudaFuncSetAttribute(quant2_kernel,
                         cudaFuncAttributeMaxDynamicSharedMemorySize, smem_q2);

    // 1) split weights fp32 -> bf16 hi/lo
    const int n4 = (IDIM / 4) * HDIM;
    split_one_kernel<<<1024, 256>>>((const float4*)wg, (__nv_bfloat162*)p_wgh,
                                    (__nv_bfloat162*)p_wgl, n4);
    split_one_kernel<<<1024, 256>>>((const float4*)wu, (__nv_bfloat162*)p_wuh,
                                    (__nv_bfloat162*)p_wul, n4);
    split_one_kernel<<<1024, 256>>>((const float4*)wd, (__nv_bfloat162*)p_wdh,
                                    (__nv_bfloat162*)p_wdl, n4);

    // 2) per-token fake-quant of x
    quant_x_kernel<<<M_TOK, 256>>>(x);

    // 3) fused gate/up GEMM + SwiGLU epilogue -> inter (fp32)
    dim3 g1(M_TOK / 128, IDIM / 128);   // (32, 112), m fastest
    hgemm_kernel<4, true><<<g1, 256, smem_fused>>>(
        (const __nv_bfloat16*)p_xq,
        (const __nv_bfloat16*)p_wgh, (const __nv_bfloat16*)p_wgl,
        (const __nv_bfloat16*)p_wuh, (const __nv_bfloat16*)p_wul,
        (const float*)p_xs, (float*)p_inter, HDIM, IDIM);

    // 4) fake-quant of inter
    quant2_kernel<<<M_TOK, 512, smem_q2>>>();

    // 5) down GEMM -> out
    dim3 g3(M_TOK / 128, HDIM / 128);   // (32, 32)
    hgemm_kernel<2, false><<<g3, 256, smem_down>>>(
        (const __nv_bfloat16*)p_q2,
        (const __nv_bfloat16*)p_wdh, (const __nv_bfloat16*)p_wdl,
        (const __nv_bfloat16*)p_wdh, (const __nv_bfloat16*)p_wdl,
        (const float*)p_s2, out, IDIM, HDIM);
}